// round 11
// baseline (speedup 1.0000x reference)
#include <cuda_runtime.h>

#define BT 320

typedef unsigned long long ull;

__device__ __forceinline__ ull pack2(float a, float b) {
    ull r;
    asm("mov.b64 %0, {%1, %2};" : "=l"(r) : "f"(a), "f"(b));
    return r;
}
__device__ __forceinline__ void unpack2(ull v, float& a, float& b) {
    asm("mov.b64 {%0, %1}, %2;" : "=f"(a), "=f"(b) : "l"(v));
}
__device__ __forceinline__ ull fma2(ull a, ull b, ull c) {
    ull d;
    asm("fma.rn.f32x2 %0, %1, %2, %3;" : "=l"(d) : "l"(a), "l"(b), "l"(c));
    return d;
}

// layer-2 step for FOUR edges at one W2 row (padded [30][16]); weights loaded once
#define EDGE4_STEP(ax, b1x, b2x, b3x, b4x, W2ROW)                            \
    {                                                                        \
        float va = fmaxf((ax) + (b1x), 0.f);                                 \
        float vb = fmaxf((ax) + (b2x), 0.f);                                 \
        float vc = fmaxf((ax) + (b3x), 0.f);                                 \
        float vd = fmaxf((ax) + (b4x), 0.f);                                 \
        ull vva = pack2(va, va);                                             \
        ull vvb = pack2(vb, vb);                                             \
        ull vvc = pack2(vc, vc);                                             \
        ull vvd = pack2(vd, vd);                                             \
        const ulonglong2* w = (const ulonglong2*)(W2ROW);                    \
        ulonglong2 wA = w[0], wB = w[1];                                     \
        h2a[0] = fma2(vva, wA.x, h2a[0]); h2b[0] = fma2(vvb, wA.x, h2b[0]);  \
        h2c[0] = fma2(vvc, wA.x, h2c[0]); h2d[0] = fma2(vvd, wA.x, h2d[0]);  \
        h2a[1] = fma2(vva, wA.y, h2a[1]); h2b[1] = fma2(vvb, wA.y, h2b[1]);  \
        h2c[1] = fma2(vvc, wA.y, h2c[1]); h2d[1] = fma2(vvd, wA.y, h2d[1]);  \
        h2a[2] = fma2(vva, wB.x, h2a[2]); h2b[2] = fma2(vvb, wB.x, h2b[2]);  \
        h2c[2] = fma2(vvc, wB.x, h2c[2]); h2d[2] = fma2(vvd, wB.x, h2d[2]);  \
        h2a[3] = fma2(vva, wB.y, h2a[3]); h2b[3] = fma2(vvb, wB.y, h2b[3]);  \
        h2c[3] = fma2(vvc, wB.y, h2c[3]); h2d[3] = fma2(vvd, wB.y, h2d[3]);  \
        w = (const ulonglong2*)((W2ROW) + 8);                                \
        wA = w[0]; wB = w[1];                                                \
        h2a[4] = fma2(vva, wA.x, h2a[4]); h2b[4] = fma2(vvb, wA.x, h2b[4]);  \
        h2c[4] = fma2(vvc, wA.x, h2c[4]); h2d[4] = fma2(vvd, wA.x, h2d[4]);  \
        h2a[5] = fma2(vva, wA.y, h2a[5]); h2b[5] = fma2(vvb, wA.y, h2b[5]);  \
        h2c[5] = fma2(vvc, wA.y, h2c[5]); h2d[5] = fma2(vvd, wA.y, h2d[5]);  \
        h2a[6] = fma2(vva, wB.x, h2a[6]); h2b[6] = fma2(vvb, wB.x, h2b[6]);  \
        h2c[6] = fma2(vvc, wB.x, h2c[6]); h2d[6] = fma2(vvd, wB.x, h2d[6]);  \
        h2a[7] = fma2(vva, wB.y, h2a[7]); h2b[7] = fma2(vvb, wB.y, h2b[7]);  \
        h2c[7] = fma2(vvc, wB.y, h2c[7]); h2d[7] = fma2(vvd, wB.y, h2d[7]);  \
    }

#define EDGE1_STEP(ax, bx, W2ROW)                                            \
    {                                                                        \
        float v = fmaxf((ax) + (bx), 0.f);                                   \
        ull vv = pack2(v, v);                                                \
        const ulonglong2* w = (const ulonglong2*)(W2ROW);                    \
        ulonglong2 wA = w[0], wB = w[1];                                     \
        h2p[0] = fma2(vv, wA.x, h2p[0]);                                     \
        h2p[1] = fma2(vv, wA.y, h2p[1]);                                     \
        h2p[2] = fma2(vv, wB.x, h2p[2]);                                     \
        h2p[3] = fma2(vv, wB.y, h2p[3]);                                     \
        w = (const ulonglong2*)((W2ROW) + 8);                                \
        wA = w[0]; wB = w[1];                                                \
        h2p[4] = fma2(vv, wA.x, h2p[4]);                                     \
        h2p[5] = fma2(vv, wA.y, h2p[5]);                                     \
        h2p[6] = fma2(vv, wB.x, h2p[6]);                                     \
        h2p[7] = fma2(vv, wB.y, h2p[7]);                                     \
    }

// layer-3 for a PAIR of edges sharing W3 loads; accumulates relu(h3) into acc[6]
#define LAYER3_PAIR(H2X, H2Y)                                                \
    {                                                                        \
        float h3a[6], h3b[6];                                                \
        _Pragma("unroll")                                                    \
        for (int m = 0; m < 6; m++) { h3a[m] = s_b3[m]; h3b[m] = s_b3[m]; }  \
        _Pragma("unroll 4")                                                  \
        for (int p = 0; p < 8; p++) {                                        \
            float a1, c1, a2, c2;                                            \
            unpack2(H2X[p], a1, c1);                                         \
            unpack2(H2Y[p], a2, c2);                                         \
            float va1 = fmaxf(a1, 0.f), vc1 = fmaxf(c1, 0.f);                \
            float va2 = fmaxf(a2, 0.f), vc2 = fmaxf(c2, 0.f);                \
            const float4* wq = (const float4*)(s_W3 + (2 * p) * 8);          \
            float4 wa = wq[0], wb = wq[1];                                   \
            h3a[0] = fmaf(va1, wa.x, h3a[0]); h3b[0] = fmaf(va2, wa.x, h3b[0]); \
            h3a[1] = fmaf(va1, wa.y, h3a[1]); h3b[1] = fmaf(va2, wa.y, h3b[1]); \
            h3a[2] = fmaf(va1, wa.z, h3a[2]); h3b[2] = fmaf(va2, wa.z, h3b[2]); \
            h3a[3] = fmaf(va1, wa.w, h3a[3]); h3b[3] = fmaf(va2, wa.w, h3b[3]); \
            h3a[4] = fmaf(va1, wb.x, h3a[4]); h3b[4] = fmaf(va2, wb.x, h3b[4]); \
            h3a[5] = fmaf(va1, wb.y, h3a[5]); h3b[5] = fmaf(va2, wb.y, h3b[5]); \
            wq = (const float4*)(s_W3 + (2 * p + 1) * 8);                    \
            wa = wq[0]; wb = wq[1];                                          \
            h3a[0] = fmaf(vc1, wa.x, h3a[0]); h3b[0] = fmaf(vc2, wa.x, h3b[0]); \
            h3a[1] = fmaf(vc1, wa.y, h3a[1]); h3b[1] = fmaf(vc2, wa.y, h3b[1]); \
            h3a[2] = fmaf(vc1, wa.z, h3a[2]); h3b[2] = fmaf(vc2, wa.z, h3b[2]); \
            h3a[3] = fmaf(vc1, wa.w, h3a[3]); h3b[3] = fmaf(vc2, wa.w, h3b[3]); \
            h3a[4] = fmaf(vc1, wb.x, h3a[4]); h3b[4] = fmaf(vc2, wb.x, h3b[4]); \
            h3a[5] = fmaf(vc1, wb.y, h3a[5]); h3b[5] = fmaf(vc2, wb.y, h3b[5]); \
        }                                                                    \
        _Pragma("unroll")                                                    \
        for (int m = 0; m < 6; m++)                                          \
            acc[m] += fmaxf(h3a[m], 0.f) + fmaxf(h3b[m], 0.f);               \
    }

__global__ __launch_bounds__(320, 2) void convintnet_kernel(
    const float* __restrict__ x,
    const float* __restrict__ bn_gamma, const float* __restrict__ bn_beta,
    const float* __restrict__ bn_mean, const float* __restrict__ bn_var,
    const float* __restrict__ eW1, const float* __restrict__ eb1,
    const float* __restrict__ eW2, const float* __restrict__ eb2,
    const float* __restrict__ eW3, const float* __restrict__ eb3,
    const float* __restrict__ dW1, const float* __restrict__ db1,
    const float* __restrict__ dW2, const float* __restrict__ db2,
    const float* __restrict__ dW3, const float* __restrict__ db3,
    const float* __restrict__ aW1, const float* __restrict__ ab1,
    const float* __restrict__ aW2, const float* __restrict__ ab2,
    float* __restrict__ out)
{
    // ---- shared memory ----
    __shared__ __align__(16) float s_xn[800];     // [50][16]
    __shared__ __align__(16) float s_buf[3100];   // A=[50] stride 31; B at +1550; reused as d1=[50][45]
    __shared__ __align__(16) float s_eff[304];    // [50][6]
    __shared__ __align__(16) float s_d2[1100];    // [50][22]
    __shared__ __align__(16) float s_part[1808];  // edge partials [6][50][6]; reused as d3
    __shared__ __align__(16) float s_W1a[480], s_W1b[480], s_eb1[32];
    __shared__ __align__(16) float s_W2[512];     // [32][16] padded (col 15 = 0; rows 30,31 = 0)
    __shared__ __align__(16) float s_b2[16];      // b2[15]=0
    __shared__ __align__(16) float s_W3[128];     // [16][8] padded (row 15, cols 6,7 = 0)
    __shared__ __align__(16) float s_b3[8];
    __shared__ __align__(16) float s_dW1[992], s_db1[48];
    __shared__ __align__(16) float s_dW2[992], s_db2[24];
    __shared__ __align__(16) float s_dW3[132], s_db3[8];
    __shared__ __align__(16) float s_aW1[288], s_ab1[48];
    __shared__ __align__(16) float s_aW2[240], s_ab2[8];
    __shared__ __align__(16) float s_bns[16], s_bnt[16];
    __shared__ __align__(16) float s_dsum[8];
    __shared__ __align__(16) float s_a1[48];

    const int tid = threadIdx.x;
    const int b   = blockIdx.x;

    // ---- params into smem ----
    for (int i = tid; i < 480; i += BT) s_W1a[i] = eW1[i];
    for (int i = tid; i < 480; i += BT) s_W1b[i] = eW1[480 + i];
    for (int i = tid; i < 512; i += BT) {
        int r = i >> 4, c = i & 15;
        s_W2[i] = (r < 30 && c < 15) ? eW2[r * 15 + c] : 0.f;
    }
    for (int i = tid; i < 128; i += BT) {
        int r = i >> 3, c = i & 7;
        s_W3[i] = (r < 15 && c < 6) ? eW3[r * 6 + c] : 0.f;
    }
    for (int i = tid; i < 990; i += BT) s_dW1[i] = dW1[i];
    for (int i = tid; i < 990; i += BT) s_dW2[i] = dW2[i];
    for (int i = tid; i < 132; i += BT) s_dW3[i] = dW3[i];
    for (int i = tid; i < 288; i += BT) s_aW1[i] = aW1[i];
    for (int i = tid; i < 240; i += BT) s_aW2[i] = aW2[i];
    if (tid < 30) s_eb1[tid] = eb1[tid];
    if (tid < 45) s_db1[tid] = db1[tid];
    if (tid < 22) s_db2[tid] = db2[tid];
    if (tid < 6)  s_db3[tid] = db3[tid];
    if (tid < 48) s_ab1[tid] = ab1[tid];
    if (tid < 5)  s_ab2[tid] = ab2[tid];
    if (tid < 16) {
        s_b2[tid] = (tid < 15) ? eb2[tid] : 0.f;
        float sc = bn_gamma[tid] * rsqrtf(bn_var[tid] + 1e-3f);
        s_bns[tid] = sc;
        s_bnt[tid] = bn_beta[tid] - bn_mean[tid] * sc;
    }
    if (tid < 8) s_b3[tid] = (tid < 6) ? eb3[tid] : 0.f;
    __syncthreads();

    // ---- batchnorm ----
    const float* xb = x + b * 800;
    for (int i = tid; i < 800; i += BT) {
        int f = i & 15;
        s_xn[i] = fmaf(xb[i], s_bns[f], s_bnt[f]);
    }
    __syncthreads();

    // ---- factored edge layer 1: A[n]=xn[n]@W1_top+eb1, B[n]=xn[n]@W1_bot (row stride 31) ----
    for (int i = tid; i < 3000; i += BT) {
        int half = (i >= 1500);
        int idx  = half ? (i - 1500) : i;
        int n = idx / 30, k = idx - n * 30;
        const float* W = half ? s_W1b : s_W1a;
        float acc = half ? 0.f : s_eb1[k];
        const float* xr = s_xn + n * 16;
        #pragma unroll
        for (int f = 0; f < 16; f++) acc = fmaf(xr[f], W[f * 30 + k], acc);
        s_buf[(half ? 1550 : 0) + n * 31 + k] = acc;
    }
    __syncthreads();

    // ---- edge MLP: 6 threads/receiver; senders in QUADS (one weight load serves 4 edges) ----
    if (tid < 300) {
        const int r = tid / 6, sub = tid - r * 6;
        const float* Ar = s_buf + r * 31;

        float acc[6];
        #pragma unroll
        for (int m = 0; m < 6; m++) acc[m] = 0.f;

        int kk = sub;
        #pragma unroll 1
        for (; kk + 18 < 49; kk += 24) {
            const int k1 = kk, k2 = kk + 6, k3 = kk + 12, k4 = kk + 18;
            const int s1 = k1 + (k1 >= r);
            const int s2 = k2 + (k2 >= r);
            const int s3 = k3 + (k3 >= r);
            const int s4 = k4 + (k4 >= r);
            const float* B1 = s_buf + 1550 + s1 * 31;
            const float* B2 = s_buf + 1550 + s2 * 31;
            const float* B3 = s_buf + 1550 + s3 * 31;
            const float* B4 = s_buf + 1550 + s4 * 31;

            ull h2a[8], h2b[8], h2c[8], h2d[8];
            {
                const ull* b2q = (const ull*)s_b2;
                #pragma unroll
                for (int p = 0; p < 8; p++) {
                    ull v = b2q[p];
                    h2a[p] = v; h2b[p] = v; h2c[p] = v; h2d[p] = v;
                }
            }

            #pragma unroll 2
            for (int i = 0; i < 30; i++) {
                float a0 = Ar[i];
                EDGE4_STEP(a0, B1[i], B2[i], B3[i], B4[i], s_W2 + i * 16)
            }

            LAYER3_PAIR(h2a, h2b)
            LAYER3_PAIR(h2c, h2d)
        }

        // remaining singles (0, 1, or 2 of them)
        #pragma unroll 1
        for (; kk < 49; kk += 6) {
            const int s = kk + (kk >= r);
            const float* Bs = s_buf + 1550 + s * 31;

            ull h2p[8];
            {
                const ull* b2q = (const ull*)s_b2;
                #pragma unroll
                for (int p = 0; p < 8; p++) h2p[p] = b2q[p];
            }

            #pragma unroll 5
            for (int i = 0; i < 30; i++) {
                EDGE1_STEP(Ar[i], Bs[i], s_W2 + i * 16)
            }

            float h3[6];
            #pragma unroll
            for (int m = 0; m < 6; m++) h3[m] = s_b3[m];

            #pragma unroll 4
            for (int p = 0; p < 8; p++) {
                float a, c;
                unpack2(h2p[p], a, c);
                float va = fmaxf(a, 0.f);
                float vc = fmaxf(c, 0.f);
                const float4* wq = (const float4*)(s_W3 + (2 * p) * 8);
                float4 wa = wq[0], wb = wq[1];
                h3[0] = fmaf(va, wa.x, h3[0]); h3[1] = fmaf(va, wa.y, h3[1]);
                h3[2] = fmaf(va, wa.z, h3[2]); h3[3] = fmaf(va, wa.w, h3[3]);
                h3[4] = fmaf(va, wb.x, h3[4]); h3[5] = fmaf(va, wb.y, h3[5]);
                wq = (const float4*)(s_W3 + (2 * p + 1) * 8);
                wa = wq[0]; wb = wq[1];
                h3[0] = fmaf(vc, wa.x, h3[0]); h3[1] = fmaf(vc, wa.y, h3[1]);
                h3[2] = fmaf(vc, wa.z, h3[2]); h3[3] = fmaf(vc, wa.w, h3[3]);
                h3[4] = fmaf(vc, wb.x, h3[4]); h3[5] = fmaf(vc, wb.y, h3[5]);
            }

            #pragma unroll
            for (int m = 0; m < 6; m++) acc[m] += fmaxf(h3[m], 0.f);
        }

        float* dst = s_part + (sub * 50 + r) * 6;
        #pragma unroll
        for (int m = 0; m < 6; m++) dst[m] = acc[m];
    }
    __syncthreads();

    // ---- reduce partials: s_eff[r*6+m] = sum over 6 subs ----
    for (int i = tid; i < 300; i += BT) {
        float v = s_part[i];
        #pragma unroll
        for (int p = 1; p < 6; p++) v += s_part[p * 300 + i];
        s_eff[i] = v;
    }
    __syncthreads();

    // ---- dynamics layer 1: [xn | eff] (22) -> 45 (reuse s_buf as d1) ----
    for (int i = tid; i < 2250; i += BT) {
        int n = i / 45, o = i - n * 45;
        float acc = s_db1[o];
        const float* xr = s_xn + n * 16;
        #pragma unroll
        for (int f = 0; f < 16; f++) acc = fmaf(xr[f], s_dW1[f * 45 + o], acc);
        const float* er = s_eff + n * 6;
        #pragma unroll
        for (int m = 0; m < 6; m++) acc = fmaf(er[m], s_dW1[(16 + m) * 45 + o], acc);
        s_buf[i] = fmaxf(acc, 0.f);
    }
    __syncthreads();

    // ---- dynamics layer 2: 45 -> 22 ----
    for (int i = tid; i < 1100; i += BT) {
        int n = i / 22, o = i - n * 22;
        float acc = s_db2[o];
        const float* dr = s_buf + n * 45;
        #pragma unroll 9
        for (int j = 0; j < 45; j++) acc = fmaf(dr[j], s_dW2[j * 22 + o], acc);
        s_d2[i] = fmaxf(acc, 0.f);
    }
    __syncthreads();

    // ---- dynamics layer 3: 22 -> 6 per node, staged to smem ----
    for (int i = tid; i < 300; i += BT) {
        int n = i / 6, o = i - n * 6;
        float acc = s_db3[o];
        const float* dr = s_d2 + n * 22;
        #pragma unroll 11
        for (int j = 0; j < 22; j++) acc = fmaf(dr[j], s_dW3[j * 6 + o], acc);
        s_part[i] = fmaxf(acc, 0.f);
    }
    __syncthreads();

    // ---- sum over nodes: 6 threads x 50 ----
    if (tid < 6) {
        float v = 0.f;
        #pragma unroll 10
        for (int n = 0; n < 50; n++) v += s_part[n * 6 + tid];
        s_dsum[tid] = v;
    }
    __syncthreads();

    // ---- classifier layer 1: 6 -> 48 ----
    if (tid < 48) {
        float acc = s_ab1[tid];
        #pragma unroll
        for (int j = 0; j < 6; j++) acc = fmaf(s_dsum[j], s_aW1[j * 48 + tid], acc);
        s_a1[tid] = fmaxf(acc, 0.f);
    }
    __syncthreads();

    // ---- classifier layer 2 + softmax ----
    if (tid == 0) {
        float lg[5];
        #pragma unroll
        for (int o = 0; o < 5; o++) {
            float acc = s_ab2[o];
            #pragma unroll
            for (int j = 0; j < 48; j++) acc = fmaf(s_a1[j], s_aW2[j * 5 + o], acc);
            lg[o] = acc;
        }
        float mx = lg[0];
        #pragma unroll
        for (int o = 1; o < 5; o++) mx = fmaxf(mx, lg[o]);
        float e[5], sum = 0.f;
        #pragma unroll
        for (int o = 0; o < 5; o++) { e[o] = expf(lg[o] - mx); sum += e[o]; }
        float inv = 1.f / sum;
        #pragma unroll
        for (int o = 0; o < 5; o++) out[b * 5 + o] = e[o] * inv;
    }
}

extern "C" void kernel_launch(void* const* d_in, const int* in_sizes, int n_in,
                              void* d_out, int out_size) {
    const int B = in_sizes[0] / 800;  // x is [B, 50, 16]
    convintnet_kernel<<<B, BT>>>(
        (const float*)d_in[0],
        (const float*)d_in[1],  (const float*)d_in[2],
        (const float*)d_in[3],  (const float*)d_in[4],
        (const float*)d_in[5],  (const float*)d_in[6],
        (const float*)d_in[7],  (const float*)d_in[8],
        (const float*)d_in[9],  (const float*)d_in[10],
        (const float*)d_in[11], (const float*)d_in[12],
        (const float*)d_in[13], (const float*)d_in[14],
        (const float*)d_in[15], (const float*)d_in[16],
        (const float*)d_in[17], (const float*)d_in[18],
        (const float*)d_in[19], (const float*)d_in[20],
        (float*)d_out);
}

// round 12
// speedup vs baseline: 1.1508x; 1.1508x over previous
#include <cuda_runtime.h>

#define BT 512

typedef unsigned long long ull;

__device__ __forceinline__ ull pack2(float a, float b) {
    ull r;
    asm("mov.b64 %0, {%1, %2};" : "=l"(r) : "f"(a), "f"(b));
    return r;
}
__device__ __forceinline__ void unpack2(ull v, float& a, float& b) {
    asm("mov.b64 {%0, %1}, %2;" : "=f"(a), "=f"(b) : "l"(v));
}
__device__ __forceinline__ ull fma2(ull a, ull b, ull c) {
    ull d;
    asm("fma.rn.f32x2 %0, %1, %2, %3;" : "=l"(d) : "l"(a), "l"(b), "l"(c));
    return d;
}

// dual-edge layer-2 step at one W2 row (padded [32][16]); va/vb already relu'd+packed
#define EDGE2_CORE(vva, vvb, W2ROW)                                          \
    {                                                                        \
        const ulonglong2* w = (const ulonglong2*)(W2ROW);                    \
        ulonglong2 wA = w[0], wB = w[1];                                     \
        h2a[0] = fma2(vva, wA.x, h2a[0]); h2b[0] = fma2(vvb, wA.x, h2b[0]);  \
        h2a[1] = fma2(vva, wA.y, h2a[1]); h2b[1] = fma2(vvb, wA.y, h2b[1]);  \
        h2a[2] = fma2(vva, wB.x, h2a[2]); h2b[2] = fma2(vvb, wB.x, h2b[2]);  \
        h2a[3] = fma2(vva, wB.y, h2a[3]); h2b[3] = fma2(vvb, wB.y, h2b[3]);  \
        w = (const ulonglong2*)((W2ROW) + 8);                                \
        wA = w[0]; wB = w[1];                                                \
        h2a[4] = fma2(vva, wA.x, h2a[4]); h2b[4] = fma2(vvb, wA.x, h2b[4]);  \
        h2a[5] = fma2(vva, wA.y, h2a[5]); h2b[5] = fma2(vvb, wA.y, h2b[5]);  \
        h2a[6] = fma2(vva, wB.x, h2a[6]); h2b[6] = fma2(vvb, wB.x, h2b[6]);  \
        h2a[7] = fma2(vva, wB.y, h2a[7]); h2b[7] = fma2(vvb, wB.y, h2b[7]);  \
    }

#define EDGE1_STEP(ax, bx, W2ROW)                                            \
    {                                                                        \
        float v = fmaxf((ax) + (bx), 0.f);                                   \
        ull vv = pack2(v, v);                                                \
        const ulonglong2* w = (const ulonglong2*)(W2ROW);                    \
        ulonglong2 wA = w[0], wB = w[1];                                     \
        h2p[0] = fma2(vv, wA.x, h2p[0]);                                     \
        h2p[1] = fma2(vv, wA.y, h2p[1]);                                     \
        h2p[2] = fma2(vv, wB.x, h2p[2]);                                     \
        h2p[3] = fma2(vv, wB.y, h2p[3]);                                     \
        w = (const ulonglong2*)((W2ROW) + 8);                                \
        wA = w[0]; wB = w[1];                                                \
        h2p[4] = fma2(vv, wA.x, h2p[4]);                                     \
        h2p[5] = fma2(vv, wA.y, h2p[5]);                                     \
        h2p[6] = fma2(vv, wB.x, h2p[6]);                                     \
        h2p[7] = fma2(vv, wB.y, h2p[7]);                                     \
    }

__global__ __launch_bounds__(512, 2) void convintnet_kernel(
    const float* __restrict__ x,
    const float* __restrict__ bn_gamma, const float* __restrict__ bn_beta,
    const float* __restrict__ bn_mean, const float* __restrict__ bn_var,
    const float* __restrict__ eW1, const float* __restrict__ eb1,
    const float* __restrict__ eW2, const float* __restrict__ eb2,
    const float* __restrict__ eW3, const float* __restrict__ eb3,
    const float* __restrict__ dW1, const float* __restrict__ db1,
    const float* __restrict__ dW2, const float* __restrict__ db2,
    const float* __restrict__ dW3, const float* __restrict__ db3,
    const float* __restrict__ aW1, const float* __restrict__ ab1,
    const float* __restrict__ aW2, const float* __restrict__ ab2,
    float* __restrict__ out)
{
    // ---- shared memory ----
    __shared__ __align__(16) float s_xn[800];     // [50][16]
    __shared__ __align__(16) float s_buf[3112];   // A=[50] stride 31 at 0; Bt=[30][52] at 1550; reused as d1
    __shared__ __align__(16) float s_eff[304];    // [50][6]
    __shared__ __align__(16) float s_d2[1100];    // [50][22]
    __shared__ __align__(16) float s_part[3008];  // edge partials [10][50][6]; reused as d3
    __shared__ __align__(16) float s_W1a[480], s_W1b[480], s_eb1[32];
    __shared__ __align__(16) float s_W2[512];     // [32][16] padded (col 15 = 0; rows 30,31 = 0)
    __shared__ __align__(16) float s_b2[16];      // b2[15]=0
    __shared__ __align__(16) float s_W3[128];     // [16][8] padded (row 15, cols 6,7 = 0)
    __shared__ __align__(16) float s_b3[8];
    __shared__ __align__(16) float s_dW1[992], s_db1[48];
    __shared__ __align__(16) float s_dW2[992], s_db2[24];
    __shared__ __align__(16) float s_dW3[132], s_db3[8];
    __shared__ __align__(16) float s_aW1[288], s_ab1[48];
    __shared__ __align__(16) float s_aW2[240], s_ab2[8];
    __shared__ __align__(16) float s_bns[16], s_bnt[16];
    __shared__ __align__(16) float s_dsum[8];
    __shared__ __align__(16) float s_a1[48];

    const int tid = threadIdx.x;
    const int b   = blockIdx.x;

    // ---- params into smem ----
    for (int i = tid; i < 480; i += BT) s_W1a[i] = eW1[i];
    for (int i = tid; i < 480; i += BT) s_W1b[i] = eW1[480 + i];
    for (int i = tid; i < 512; i += BT) {
        int r = i >> 4, c = i & 15;
        s_W2[i] = (r < 30 && c < 15) ? eW2[r * 15 + c] : 0.f;
    }
    for (int i = tid; i < 128; i += BT) {
        int r = i >> 3, c = i & 7;
        s_W3[i] = (r < 15 && c < 6) ? eW3[r * 6 + c] : 0.f;
    }
    for (int i = tid; i < 990; i += BT) s_dW1[i] = dW1[i];
    for (int i = tid; i < 990; i += BT) s_dW2[i] = dW2[i];
    for (int i = tid; i < 132; i += BT) s_dW3[i] = dW3[i];
    for (int i = tid; i < 288; i += BT) s_aW1[i] = aW1[i];
    for (int i = tid; i < 240; i += BT) s_aW2[i] = aW2[i];
    if (tid < 30) s_eb1[tid] = eb1[tid];
    if (tid < 45) s_db1[tid] = db1[tid];
    if (tid < 22) s_db2[tid] = db2[tid];
    if (tid < 6)  s_db3[tid] = db3[tid];
    if (tid < 48) s_ab1[tid] = ab1[tid];
    if (tid < 5)  s_ab2[tid] = ab2[tid];
    if (tid < 16) {
        s_b2[tid] = (tid < 15) ? eb2[tid] : 0.f;
        float sc = bn_gamma[tid] * rsqrtf(bn_var[tid] + 1e-3f);
        s_bns[tid] = sc;
        s_bnt[tid] = bn_beta[tid] - bn_mean[tid] * sc;
    }
    if (tid < 8) s_b3[tid] = (tid < 6) ? eb3[tid] : 0.f;
    __syncthreads();

    // ---- batchnorm ----
    const float* xb = x + b * 800;
    for (int i = tid; i < 800; i += BT) {
        int f = i & 15;
        s_xn[i] = fmaf(xb[i], s_bns[f], s_bnt[f]);
    }
    __syncthreads();

    // ---- factored edge layer 1: A[n] row stride 31; B TRANSPOSED Bt[k][n] stride 52 ----
    for (int i = tid; i < 3000; i += BT) {
        int half = (i >= 1500);
        int idx  = half ? (i - 1500) : i;
        int n = idx / 30, k = idx - n * 30;
        const float* W = half ? s_W1b : s_W1a;
        float acc = half ? 0.f : s_eb1[k];
        const float* xr = s_xn + n * 16;
        #pragma unroll
        for (int f = 0; f < 16; f++) acc = fmaf(xr[f], W[f * 30 + k], acc);
        if (half) s_buf[1550 + k * 52 + n] = acc;   // Bt[k][n]
        else      s_buf[n * 31 + k] = acc;          // A[n][k]
    }
    __syncthreads();

    // ---- edge MLP: 10 threads/receiver; CONTIGUOUS sender pairs via float2 on Bt ----
    // Covers ALL 50 senders (incl. self-edge, subtracted later). Pair j = senders (2j, 2j+1).
    // subs 0-4: pairs {sub, sub+10, sub+20}; subs 5-9: pairs {sub, sub+10}.
    if (tid < 500) {
        const int r = tid / 10, sub = tid - r * 10;
        const float* Ar = s_buf + r * 31;
        const int npairs = (sub < 5) ? 3 : 2;

        float acc[6];
        #pragma unroll
        for (int m = 0; m < 6; m++) acc[m] = 0.f;

        #pragma unroll 1
        for (int t = 0; t < npairs; t++) {
            const int j = sub + 10 * t;
            const float* Bp = s_buf + 1550 + 2 * j;   // Bt column base; row stride 52

            ull h2a[8], h2b[8];
            {
                const ull* b2q = (const ull*)s_b2;
                #pragma unroll
                for (int p = 0; p < 8; p++) { h2a[p] = b2q[p]; h2b[p] = b2q[p]; }
            }

            #pragma unroll 3
            for (int i = 0; i < 30; i++) {
                float a0 = Ar[i];
                float2 bb = *(const float2*)(Bp + i * 52);
                float va = fmaxf(a0 + bb.x, 0.f);
                float vb = fmaxf(a0 + bb.y, 0.f);
                ull vva = pack2(va, va);
                ull vvb = pack2(vb, vb);
                EDGE2_CORE(vva, vvb, s_W2 + i * 16)
            }

            float h3a[6], h3b[6];
            #pragma unroll
            for (int m = 0; m < 6; m++) { h3a[m] = s_b3[m]; h3b[m] = s_b3[m]; }

            #pragma unroll 4
            for (int p = 0; p < 8; p++) {
                float a1, c1, a2, c2;
                unpack2(h2a[p], a1, c1);
                unpack2(h2b[p], a2, c2);
                float va1 = fmaxf(a1, 0.f), vc1 = fmaxf(c1, 0.f);
                float va2 = fmaxf(a2, 0.f), vc2 = fmaxf(c2, 0.f);
                const float4* wq = (const float4*)(s_W3 + (2 * p) * 8);
                float4 wa = wq[0], wb = wq[1];
                h3a[0] = fmaf(va1, wa.x, h3a[0]); h3b[0] = fmaf(va2, wa.x, h3b[0]);
                h3a[1] = fmaf(va1, wa.y, h3a[1]); h3b[1] = fmaf(va2, wa.y, h3b[1]);
                h3a[2] = fmaf(va1, wa.z, h3a[2]); h3b[2] = fmaf(va2, wa.z, h3b[2]);
                h3a[3] = fmaf(va1, wa.w, h3a[3]); h3b[3] = fmaf(va2, wa.w, h3b[3]);
                h3a[4] = fmaf(va1, wb.x, h3a[4]); h3b[4] = fmaf(va2, wb.x, h3b[4]);
                h3a[5] = fmaf(va1, wb.y, h3a[5]); h3b[5] = fmaf(va2, wb.y, h3b[5]);
                wq = (const float4*)(s_W3 + (2 * p + 1) * 8);
                wa = wq[0]; wb = wq[1];
                h3a[0] = fmaf(vc1, wa.x, h3a[0]); h3b[0] = fmaf(vc2, wa.x, h3b[0]);
                h3a[1] = fmaf(vc1, wa.y, h3a[1]); h3b[1] = fmaf(vc2, wa.y, h3b[1]);
                h3a[2] = fmaf(vc1, wa.z, h3a[2]); h3b[2] = fmaf(vc2, wa.z, h3b[2]);
                h3a[3] = fmaf(vc1, wa.w, h3a[3]); h3b[3] = fmaf(vc2, wa.w, h3b[3]);
                h3a[4] = fmaf(vc1, wb.x, h3a[4]); h3b[4] = fmaf(vc2, wb.x, h3b[4]);
                h3a[5] = fmaf(vc1, wb.y, h3a[5]); h3b[5] = fmaf(vc2, wb.y, h3b[5]);
            }

            #pragma unroll
            for (int m = 0; m < 6; m++)
                acc[m] += fmaxf(h3a[m], 0.f) + fmaxf(h3b[m], 0.f);
        }

        float* dst = s_part + (sub * 50 + r) * 6;
        #pragma unroll
        for (int m = 0; m < 6; m++) dst[m] = acc[m];
    }
    __syncthreads();

    // ---- reduce partials: s_eff[r*6+m] = sum over 10 subs ----
    for (int i = tid; i < 300; i += BT) {
        float v = s_part[i];
        #pragma unroll
        for (int p = 1; p < 10; p++) v += s_part[p * 300 + i];
        s_eff[i] = v;
    }
    __syncthreads();

    // ---- subtract the self-edge (r,r) that the full 50-sender sum included ----
    if (tid < 50) {
        const int r = tid;
        const float* Ar = s_buf + r * 31;

        ull h2p[8];
        {
            const ull* b2q = (const ull*)s_b2;
            #pragma unroll
            for (int p = 0; p < 8; p++) h2p[p] = b2q[p];
        }

        #pragma unroll 5
        for (int i = 0; i < 30; i++) {
            EDGE1_STEP(Ar[i], s_buf[1550 + i * 52 + r], s_W2 + i * 16)
        }

        float h3[6];
        #pragma unroll
        for (int m = 0; m < 6; m++) h3[m] = s_b3[m];

        #pragma unroll 4
        for (int p = 0; p < 8; p++) {
            float a, c;
            unpack2(h2p[p], a, c);
            float va = fmaxf(a, 0.f);
            float vc = fmaxf(c, 0.f);
            const float4* wq = (const float4*)(s_W3 + (2 * p) * 8);
            float4 wa = wq[0], wb = wq[1];
            h3[0] = fmaf(va, wa.x, h3[0]); h3[1] = fmaf(va, wa.y, h3[1]);
            h3[2] = fmaf(va, wa.z, h3[2]); h3[3] = fmaf(va, wa.w, h3[3]);
            h3[4] = fmaf(va, wb.x, h3[4]); h3[5] = fmaf(va, wb.y, h3[5]);
            wq = (const float4*)(s_W3 + (2 * p + 1) * 8);
            wa = wq[0]; wb = wq[1];
            h3[0] = fmaf(vc, wa.x, h3[0]); h3[1] = fmaf(vc, wa.y, h3[1]);
            h3[2] = fmaf(vc, wa.z, h3[2]); h3[3] = fmaf(vc, wa.w, h3[3]);
            h3[4] = fmaf(vc, wb.x, h3[4]); h3[5] = fmaf(vc, wb.y, h3[5]);
        }

        #pragma unroll
        for (int m = 0; m < 6; m++)
            s_eff[r * 6 + m] -= fmaxf(h3[m], 0.f);
    }
    __syncthreads();

    // ---- dynamics layer 1: [xn | eff] (22) -> 45 (reuse s_buf as d1) ----
    for (int i = tid; i < 2250; i += BT) {
        int n = i / 45, o = i - n * 45;
        float acc = s_db1[o];
        const float* xr = s_xn + n * 16;
        #pragma unroll
        for (int f = 0; f < 16; f++) acc = fmaf(xr[f], s_dW1[f * 45 + o], acc);
        const float* er = s_eff + n * 6;
        #pragma unroll
        for (int m = 0; m < 6; m++) acc = fmaf(er[m], s_dW1[(16 + m) * 45 + o], acc);
        s_buf[i] = fmaxf(acc, 0.f);
    }
    __syncthreads();

    // ---- dynamics layer 2: 45 -> 22 ----
    for (int i = tid; i < 1100; i += BT) {
        int n = i / 22, o = i - n * 22;
        float acc = s_db2[o];
        const float* dr = s_buf + n * 45;
        #pragma unroll 9
        for (int j = 0; j < 45; j++) acc = fmaf(dr[j], s_dW2[j * 22 + o], acc);
        s_d2[i] = fmaxf(acc, 0.f);
    }
    __syncthreads();

    // ---- dynamics layer 3: 22 -> 6 per node, staged to smem ----
    for (int i = tid; i < 300; i += BT) {
        int n = i / 6, o = i - n * 6;
        float acc = s_db3[o];
        const float* dr = s_d2 + n * 22;
        #pragma unroll 11
        for (int j = 0; j < 22; j++) acc = fmaf(dr[j], s_dW3[j * 6 + o], acc);
        s_part[i] = fmaxf(acc, 0.f);
    }
    __syncthreads();

    // ---- sum over nodes: 6 threads x 50 ----
    if (tid < 6) {
        float v = 0.f;
        #pragma unroll 10
        for (int n = 0; n < 50; n++) v += s_part[n * 6 + tid];
        s_dsum[tid] = v;
    }
    __syncthreads();

    // ---- classifier layer 1: 6 -> 48 ----
    if (tid < 48) {
        float acc = s_ab1[tid];
        #pragma unroll
        for (int j = 0; j < 6; j++) acc = fmaf(s_dsum[j], s_aW1[j * 48 + tid], acc);
        s_a1[tid] = fmaxf(acc, 0.f);
    }
    __syncthreads();

    // ---- classifier layer 2 + softmax ----
    if (tid == 0) {
        float lg[5];
        #pragma unroll
        for (int o = 0; o < 5; o++) {
            float acc = s_ab2[o];
            #pragma unroll
            for (int j = 0; j < 48; j++) acc = fmaf(s_a1[j], s_aW2[j * 5 + o], acc);
            lg[o] = acc;
        }
        float mx = lg[0];
        #pragma unroll
        for (int o = 1; o < 5; o++) mx = fmaxf(mx, lg[o]);
        float e[5], sum = 0.f;
        #pragma unroll
        for (int o = 0; o < 5; o++) { e[o] = expf(lg[o] - mx); sum += e[o]; }
        float inv = 1.f / sum;
        #pragma unroll
        for (int o = 0; o < 5; o++) out[b * 5 + o] = e[o] * inv;
    }
}

extern "C" void kernel_launch(void* const* d_in, const int* in_sizes, int n_in,
                              void* d_out, int out_size) {
    const int B = in_sizes[0] / 800;  // x is [B, 50, 16]
    convintnet_kernel<<<B, BT>>>(
        (const float*)d_in[0],
        (const float*)d_in[1],  (const float*)d_in[2],
        (const float*)d_in[3],  (const float*)d_in[4],
        (const float*)d_in[5],  (const float*)d_in[6],
        (const float*)d_in[7],  (const float*)d_in[8],
        (const float*)d_in[9],  (const float*)d_in[10],
        (const float*)d_in[11], (const float*)d_in[12],
        (const float*)d_in[13], (const float*)d_in[14],
        (const float*)d_in[15], (const float*)d_in[16],
        (const float*)d_in[17], (const float*)d_in[18],
        (const float*)d_in[19], (const float*)d_in[20],
        (float*)d_out);
}

// round 13
// speedup vs baseline: 1.2547x; 1.0903x over previous
#include <cuda_runtime.h>

#define BT 512

typedef unsigned long long ull;

__device__ __forceinline__ ull pack2(float a, float b) {
    ull r;
    asm("mov.b64 %0, {%1, %2};" : "=l"(r) : "f"(a), "f"(b));
    return r;
}
__device__ __forceinline__ void unpack2(ull v, float& a, float& b) {
    asm("mov.b64 {%0, %1}, %2;" : "=f"(a), "=f"(b) : "l"(v));
}
__device__ __forceinline__ ull fma2(ull a, ull b, ull c) {
    ull d;
    asm("fma.rn.f32x2 %0, %1, %2, %3;" : "=l"(d) : "l"(a), "l"(b), "l"(c));
    return d;
}

__global__ __launch_bounds__(512, 2) void convintnet_kernel(
    const float* __restrict__ x,
    const float* __restrict__ bn_gamma, const float* __restrict__ bn_beta,
    const float* __restrict__ bn_mean, const float* __restrict__ bn_var,
    const float* __restrict__ eW1, const float* __restrict__ eb1,
    const float* __restrict__ eW2, const float* __restrict__ eb2,
    const float* __restrict__ eW3, const float* __restrict__ eb3,
    const float* __restrict__ dW1, const float* __restrict__ db1,
    const float* __restrict__ dW2, const float* __restrict__ db2,
    const float* __restrict__ dW3, const float* __restrict__ db3,
    const float* __restrict__ aW1, const float* __restrict__ ab1,
    const float* __restrict__ aW2, const float* __restrict__ ab2,
    float* __restrict__ out)
{
    // ---- shared memory ----
    __shared__ __align__(16) float s_xn[800];     // [50][16]
    __shared__ __align__(16) float s_buf[3100];   // A=[50] stride 31; B at +1550; reused as d1=[50][45]
    __shared__ __align__(16) float s_eff[304];    // [50][6]
    __shared__ __align__(16) float s_d2[1100];    // [50][22]
    __shared__ __align__(16) float s_part[3008];  // edge partials [10][50][6]; reused as d3
    __shared__ __align__(16) float s_W1a[480], s_W1b[480], s_eb1[32];
    __shared__ __align__(16) float s_W2[512];     // [32][16] padded (col 15 = 0; rows 30,31 = 0)
    __shared__ __align__(16) float s_b2[16];      // b2[15]=0
    __shared__ __align__(16) float s_W3[128];     // [16][8] padded (row 15, cols 6,7 = 0)
    __shared__ __align__(16) float s_b3[8];
    __shared__ __align__(16) float s_dW1[992], s_db1[48];
    __shared__ __align__(16) float s_dW2[992], s_db2[24];
    __shared__ __align__(16) float s_dW3[132], s_db3[8];
    __shared__ __align__(16) float s_aW1[288], s_ab1[48];
    __shared__ __align__(16) float s_aW2[240], s_ab2[8];
    __shared__ __align__(16) float s_bns[16], s_bnt[16];
    __shared__ __align__(16) float s_dsum[8];
    __shared__ __align__(16) float s_a1[48];

    const int tid = threadIdx.x;
    const int b   = blockIdx.x;

    // ---- params into smem ----
    for (int i = tid; i < 480; i += BT) s_W1a[i] = eW1[i];
    for (int i = tid; i < 480; i += BT) s_W1b[i] = eW1[480 + i];
    for (int i = tid; i < 512; i += BT) {
        int r = i >> 4, c = i & 15;
        s_W2[i] = (r < 30 && c < 15) ? eW2[r * 15 + c] : 0.f;
    }
    for (int i = tid; i < 128; i += BT) {
        int r = i >> 3, c = i & 7;
        s_W3[i] = (r < 15 && c < 6) ? eW3[r * 6 + c] : 0.f;
    }
    for (int i = tid; i < 990; i += BT) s_dW1[i] = dW1[i];
    for (int i = tid; i < 990; i += BT) s_dW2[i] = dW2[i];
    for (int i = tid; i < 132; i += BT) s_dW3[i] = dW3[i];
    for (int i = tid; i < 288; i += BT) s_aW1[i] = aW1[i];
    for (int i = tid; i < 240; i += BT) s_aW2[i] = aW2[i];
    if (tid < 30) s_eb1[tid] = eb1[tid];
    if (tid < 45) s_db1[tid] = db1[tid];
    if (tid < 22) s_db2[tid] = db2[tid];
    if (tid < 6)  s_db3[tid] = db3[tid];
    if (tid < 48) s_ab1[tid] = ab1[tid];
    if (tid < 5)  s_ab2[tid] = ab2[tid];
    if (tid < 16) {
        s_b2[tid] = (tid < 15) ? eb2[tid] : 0.f;
        float sc = bn_gamma[tid] * rsqrtf(bn_var[tid] + 1e-3f);
        s_bns[tid] = sc;
        s_bnt[tid] = bn_beta[tid] - bn_mean[tid] * sc;
    }
    if (tid < 8) s_b3[tid] = (tid < 6) ? eb3[tid] : 0.f;
    __syncthreads();

    // ---- batchnorm ----
    const float* xb = x + b * 800;
    for (int i = tid; i < 800; i += BT) {
        int f = i & 15;
        s_xn[i] = fmaf(xb[i], s_bns[f], s_bnt[f]);
    }
    __syncthreads();

    // ---- factored edge layer 1: A[n]=xn[n]@W1_top+eb1, B[n]=xn[n]@W1_bot (row stride 31) ----
    for (int i = tid; i < 3000; i += BT) {
        int half = (i >= 1500);
        int idx  = half ? (i - 1500) : i;
        int n = idx / 30, k = idx - n * 30;
        const float* W = half ? s_W1b : s_W1a;
        float acc = half ? 0.f : s_eb1[k];
        const float* xr = s_xn + n * 16;
        #pragma unroll
        for (int f = 0; f < 16; f++) acc = fmaf(xr[f], W[f * 30 + k], acc);
        s_buf[(half ? 1550 : 0) + n * 31 + k] = acc;
    }
    __syncthreads();

    // ---- edge MLP: 10 threads/receiver; senders in PAIRS; layers 2 AND 3 packed f32x2 ----
    if (tid < 500) {
        const int r = tid / 10, sub = tid - r * 10;
        const float* Ar = s_buf + r * 31;

        float acc[6];
        #pragma unroll
        for (int m = 0; m < 6; m++) acc[m] = 0.f;

        int kk = sub;
        #pragma unroll 1
        for (; kk + 10 < 49; kk += 20) {
            const int kb = kk + 10;
            const int s1 = kk + (kk >= r);
            const int s2 = kb + (kb >= r);
            const float* B1 = s_buf + 1550 + s1 * 31;
            const float* B2 = s_buf + 1550 + s2 * 31;

            ull h2a[8], h2b[8];
            {
                const ull* b2q = (const ull*)s_b2;
                #pragma unroll
                for (int p = 0; p < 8; p++) { ull v = b2q[p]; h2a[p] = v; h2b[p] = v; }
            }

            #pragma unroll 3
            for (int i = 0; i < 30; i++) {
                float a0 = Ar[i];
                float va = fmaxf(a0 + B1[i], 0.f);
                float vb = fmaxf(a0 + B2[i], 0.f);
                ull vva = pack2(va, va);
                ull vvb = pack2(vb, vb);
                const ulonglong2* w = (const ulonglong2*)(s_W2 + i * 16);
                ulonglong2 wA = w[0], wB = w[1];
                h2a[0] = fma2(vva, wA.x, h2a[0]); h2b[0] = fma2(vvb, wA.x, h2b[0]);
                h2a[1] = fma2(vva, wA.y, h2a[1]); h2b[1] = fma2(vvb, wA.y, h2b[1]);
                h2a[2] = fma2(vva, wB.x, h2a[2]); h2b[2] = fma2(vvb, wB.x, h2b[2]);
                h2a[3] = fma2(vva, wB.y, h2a[3]); h2b[3] = fma2(vvb, wB.y, h2b[3]);
                w = (const ulonglong2*)(s_W2 + i * 16 + 8);
                wA = w[0]; wB = w[1];
                h2a[4] = fma2(vva, wA.x, h2a[4]); h2b[4] = fma2(vvb, wA.x, h2b[4]);
                h2a[5] = fma2(vva, wA.y, h2a[5]); h2b[5] = fma2(vvb, wA.y, h2b[5]);
                h2a[6] = fma2(vva, wB.x, h2a[6]); h2b[6] = fma2(vvb, wB.x, h2b[6]);
                h2a[7] = fma2(vva, wB.y, h2a[7]); h2b[7] = fma2(vvb, wB.y, h2b[7]);
            }

            // ---- layer 3, PACKED: h3 pairs (0,1),(2,3),(4,5) for both edges ----
            ull h3a[3], h3b[3];
            {
                const ull* b3q = (const ull*)s_b3;
                #pragma unroll
                for (int p = 0; p < 3; p++) { ull v = b3q[p]; h3a[p] = v; h3b[p] = v; }
            }

            #pragma unroll 4
            for (int p = 0; p < 8; p++) {
                float a1, c1, a2, c2;
                unpack2(h2a[p], a1, c1);
                unpack2(h2b[p], a2, c2);
                ull vva1 = pack2(fmaxf(a1, 0.f), fmaxf(a1, 0.f));
                ull vva2 = pack2(fmaxf(a2, 0.f), fmaxf(a2, 0.f));
                ull vvc1 = pack2(fmaxf(c1, 0.f), fmaxf(c1, 0.f));
                ull vvc2 = pack2(fmaxf(c2, 0.f), fmaxf(c2, 0.f));
                const ulonglong2* w = (const ulonglong2*)(s_W3 + (2 * p) * 8);
                ulonglong2 wA = w[0], wB = w[1];   // wA.x=(w0,w1) wA.y=(w2,w3) wB.x=(w4,w5)
                h3a[0] = fma2(vva1, wA.x, h3a[0]); h3b[0] = fma2(vva2, wA.x, h3b[0]);
                h3a[1] = fma2(vva1, wA.y, h3a[1]); h3b[1] = fma2(vva2, wA.y, h3b[1]);
                h3a[2] = fma2(vva1, wB.x, h3a[2]); h3b[2] = fma2(vva2, wB.x, h3b[2]);
                w = (const ulonglong2*)(s_W3 + (2 * p + 1) * 8);
                wA = w[0]; wB = w[1];
                h3a[0] = fma2(vvc1, wA.x, h3a[0]); h3b[0] = fma2(vvc2, wA.x, h3b[0]);
                h3a[1] = fma2(vvc1, wA.y, h3a[1]); h3b[1] = fma2(vvc2, wA.y, h3b[1]);
                h3a[2] = fma2(vvc1, wB.x, h3a[2]); h3b[2] = fma2(vvc2, wB.x, h3b[2]);
            }

            #pragma unroll
            for (int p = 0; p < 3; p++) {
                float x0, x1, y0, y1;
                unpack2(h3a[p], x0, x1);
                unpack2(h3b[p], y0, y1);
                acc[2 * p]     += fmaxf(x0, 0.f) + fmaxf(y0, 0.f);
                acc[2 * p + 1] += fmaxf(x1, 0.f) + fmaxf(y1, 0.f);
            }
        }

        // tail single edge
        if (kk < 49) {
            const int s = kk + (kk >= r);
            const float* Bs = s_buf + 1550 + s * 31;

            ull h2p[8];
            {
                const ull* b2q = (const ull*)s_b2;
                #pragma unroll
                for (int p = 0; p < 8; p++) h2p[p] = b2q[p];
            }

            #pragma unroll 5
            for (int i = 0; i < 30; i++) {
                float v = fmaxf(Ar[i] + Bs[i], 0.f);
                ull vv = pack2(v, v);
                const ulonglong2* w = (const ulonglong2*)(s_W2 + i * 16);
                ulonglong2 wA = w[0], wB = w[1];
                h2p[0] = fma2(vv, wA.x, h2p[0]);
                h2p[1] = fma2(vv, wA.y, h2p[1]);
                h2p[2] = fma2(vv, wB.x, h2p[2]);
                h2p[3] = fma2(vv, wB.y, h2p[3]);
                w = (const ulonglong2*)(s_W2 + i * 16 + 8);
                wA = w[0]; wB = w[1];
                h2p[4] = fma2(vv, wA.x, h2p[4]);
                h2p[5] = fma2(vv, wA.y, h2p[5]);
                h2p[6] = fma2(vv, wB.x, h2p[6]);
                h2p[7] = fma2(vv, wB.y, h2p[7]);
            }

            ull h3p[3];
            {
                const ull* b3q = (const ull*)s_b3;
                #pragma unroll
                for (int p = 0; p < 3; p++) h3p[p] = b3q[p];
            }

            #pragma unroll 4
            for (int p = 0; p < 8; p++) {
                float a, c;
                unpack2(h2p[p], a, c);
                ull vva = pack2(fmaxf(a, 0.f), fmaxf(a, 0.f));
                ull vvc = pack2(fmaxf(c, 0.f), fmaxf(c, 0.f));
                const ulonglong2* w = (const ulonglong2*)(s_W3 + (2 * p) * 8);
                ulonglong2 wA = w[0], wB = w[1];
                h3p[0] = fma2(vva, wA.x, h3p[0]);
                h3p[1] = fma2(vva, wA.y, h3p[1]);
                h3p[2] = fma2(vva, wB.x, h3p[2]);
                w = (const ulonglong2*)(s_W3 + (2 * p + 1) * 8);
                wA = w[0]; wB = w[1];
                h3p[0] = fma2(vvc, wA.x, h3p[0]);
                h3p[1] = fma2(vvc, wA.y, h3p[1]);
                h3p[2] = fma2(vvc, wB.x, h3p[2]);
            }

            #pragma unroll
            for (int p = 0; p < 3; p++) {
                float x0, x1;
                unpack2(h3p[p], x0, x1);
                acc[2 * p]     += fmaxf(x0, 0.f);
                acc[2 * p + 1] += fmaxf(x1, 0.f);
            }
        }

        float* dst = s_part + (sub * 50 + r) * 6;
        #pragma unroll
        for (int m = 0; m < 6; m++) dst[m] = acc[m];
    }
    __syncthreads();

    // ---- reduce partials: s_eff[r*6+m] = sum over 10 subs ----
    for (int i = tid; i < 300; i += BT) {
        float v = s_part[i];
        #pragma unroll
        for (int p = 1; p < 10; p++) v += s_part[p * 300 + i];
        s_eff[i] = v;
    }
    __syncthreads();

    // ---- dynamics layer 1: [xn | eff] (22) -> 45 (reuse s_buf as d1) ----
    for (int i = tid; i < 2250; i += BT) {
        int n = i / 45, o = i - n * 45;
        float acc = s_db1[o];
        const float* xr = s_xn + n * 16;
        #pragma unroll
        for (int f = 0; f < 16; f++) acc = fmaf(xr[f], s_dW1[f * 45 + o], acc);
        const float* er = s_eff + n * 6;
        #pragma unroll
        for (int m = 0; m < 6; m++) acc = fmaf(er[m], s_dW1[(16 + m) * 45 + o], acc);
        s_buf[i] = fmaxf(acc, 0.f);
    }
    __syncthreads();

    // ---- dynamics layer 2: 45 -> 22 ----
    for (int i = tid; i < 1100; i += BT) {
        int n = i / 22, o = i - n * 22;
        float acc = s_db2[o];
        const float* dr = s_buf + n * 45;
        #pragma unroll 9
        for (int j = 0; j < 45; j++) acc = fmaf(dr[j], s_dW2[j * 22 + o], acc);
        s_d2[i] = fmaxf(acc, 0.f);
    }
    __syncthreads();

    // ---- dynamics layer 3: 22 -> 6 per node, staged to smem ----
    for (int i = tid; i < 300; i += BT) {
        int n = i / 6, o = i - n * 6;
        float acc = s_db3[o];
        const float* dr = s_d2 + n * 22;
        #pragma unroll 11
        for (int j = 0; j < 22; j++) acc = fmaf(dr[j], s_dW3[j * 6 + o], acc);
        s_part[i] = fmaxf(acc, 0.f);
    }
    __syncthreads();

    // ---- sum over nodes: 6 threads x 50 ----
    if (tid < 6) {
        float v = 0.f;
        #pragma unroll 10
        for (int n = 0; n < 50; n++) v += s_part[n * 6 + tid];
        s_dsum[tid] = v;
    }
    __syncthreads();

    // ---- classifier layer 1: 6 -> 48 ----
    if (tid < 48) {
        float acc = s_ab1[tid];
        #pragma unroll
        for (int j = 0; j < 6; j++) acc = fmaf(s_dsum[j], s_aW1[j * 48 + tid], acc);
        s_a1[tid] = fmaxf(acc, 0.f);
    }
    __syncthreads();

    // ---- classifier layer 2 + softmax ----
    if (tid == 0) {
        float lg[5];
        #pragma unroll
        for (int o = 0; o < 5; o++) {
            float acc = s_ab2[o];
            #pragma unroll
            for (int j = 0; j < 48; j++) acc = fmaf(s_a1[j], s_aW2[j * 5 + o], acc);
            lg[o] = acc;
        }
        float mx = lg[0];
        #pragma unroll
        for (int o = 1; o < 5; o++) mx = fmaxf(mx, lg[o]);
        float e[5], sum = 0.f;
        #pragma unroll
        for (int o = 0; o < 5; o++) { e[o] = expf(lg[o] - mx); sum += e[o]; }
        float inv = 1.f / sum;
        #pragma unroll
        for (int o = 0; o < 5; o++) out[b * 5 + o] = e[o] * inv;
    }
}

extern "C" void kernel_launch(void* const* d_in, const int* in_sizes, int n_in,
                              void* d_out, int out_size) {
    const int B = in_sizes[0] / 800;  // x is [B, 50, 16]
    convintnet_kernel<<<B, BT>>>(
        (const float*)d_in[0],
        (const float*)d_in[1],  (const float*)d_in[2],
        (const float*)d_in[3],  (const float*)d_in[4],
        (const float*)d_in[5],  (const float*)d_in[6],
        (const float*)d_in[7],  (const float*)d_in[8],
        (const float*)d_in[9],  (const float*)d_in[10],
        (const float*)d_in[11], (const float*)d_in[12],
        (const float*)d_in[13], (const float*)d_in[14],
        (const float*)d_in[15], (const float*)d_in[16],
        (const float*)d_in[17], (const float*)d_in[18],
        (const float*)d_in[19], (const float*)d_in[20],
        (float*)d_out);
}